// round 3
// baseline (speedup 1.0000x reference)
#include <cuda_runtime.h>
#include <math.h>

#define TSEQ 128
#define NPED 256
#define RNN  128
#define EMB  64
#define GG   16
#define OUTD 5
#define NCTA 128
#define TPB  256
#define CAP  512
#define KDIM 256
#define ASTR 260
#define BSTR 260
#define GSTR 68

// ---- persistent device scratch (no allocations allowed) ----
__device__ float d_h[2][NPED*RNN];       // double-buffered hidden state
__device__ float d_c[NPED*RNN];          // cell state (owner-exclusive update)
__device__ float d_te[2][NPED*EMB];      // double-buffered social-tensor accumulator (pre-bias, pre-relu)
__device__ float d_ie[TSEQ*NPED*EMB];    // precomputed input embeddings (relu(pos@W_emb^T+b))
__device__ int   d_pairs[TSEQ*GG*CAP];   // pair lists bucketed by (t, cell): (i<<8)|j
__device__ int   d_pcnt[TSEQ*GG];
__device__ volatile int d_sense;         // grid barrier state (returns to 0/0: even # barriers)
__device__ int d_count;

__device__ __forceinline__ void gbar(int* lsense) {
    __syncthreads();
    if (threadIdx.x == 0) {
        int s = 1 - *lsense;
        *lsense = s;
        __threadfence();
        int arrived = atomicAdd(&d_count, 1);
        if (arrived == NCTA - 1) {
            d_count = 0;
            __threadfence();
            d_sense = s;
        } else {
            while (d_sense != s) { }
        }
        __threadfence();
    }
    __syncthreads();
}

__global__ void __launch_bounds__(TPB, 1)
social_kernel(const float* __restrict__ V,
              const float* __restrict__ W_emb, const float* __restrict__ b_emb,
              const float* __restrict__ W_tens, const float* __restrict__ b_tens,
              const float* __restrict__ W_ih,  const float* __restrict__ b_ih,
              const float* __restrict__ W_hh,  const float* __restrict__ b_hh,
              const float* __restrict__ W_out, const float* __restrict__ b_out,
              float* __restrict__ out)
{
    extern __shared__ float sm[];
    float* B_s  = sm;                    // 64 x BSTR : persistent [W_ih|W_hh] column slice
    float* A_s  = B_s + 64*BSTR;         // 16 x ASTR : per-step A panel [ie|relu(te+b)|h]
    float* G_s  = A_s + 16*ASTR;         // 16 x GSTR : gates tile
    float* h_s  = G_s + 16*GSTR;         // 128       : staged h[j] for social pairs
    float* bt_s = h_s + 128;             // 64        : b_tens
    float* o_s  = bt_s + 64;             // 16        : output reduction
    __shared__ int scnt[GG];
    __shared__ int lsense;

    const int tid = threadIdx.x;
    const int b   = blockIdx.x;
    const int gt  = b*TPB + tid;

    if (tid == 0) lsense = 0;

    // ---- zero recurrent state (NPED*RNN == NCTA*TPB exactly) ----
    d_h[0][gt] = 0.f;
    d_c[gt]    = 0.f;
    if (gt < NPED*EMB) { d_te[0][gt] = 0.f; d_te[1][gt] = 0.f; }

    // ---- cache this CTA's W_tens cell-slice in registers (cell = b>>3) ----
    float wreg[32];
    {
        const int e = tid >> 2, rs = tid & 3, gc0 = b >> 3;
        const float* wp = W_tens + e*(GG*RNN) + gc0*RNN + rs*32;
        #pragma unroll
        for (int r = 0; r < 32; r++) wreg[r] = wp[r];
    }

    // ---- precompute for frame t=b: positions, sparse pair buckets, ie ----
    {
        const int t = b;
        float* xs = A_s;            // reuse A_s region
        float* ys = A_s + NPED;
        xs[tid] = V[t*NPED + tid];
        ys[tid] = V[TSEQ*NPED + t*NPED + tid];
        if (tid < GG) scnt[tid] = 0;
        __syncthreads();
        const float WB  = (float)(64.0/720.0), WBH = (float)(32.0/720.0);
        const float HBv = (float)(64.0/576.0), HBH = (float)(32.0/576.0);
        const float xi = xs[tid], yi = ys[tid];
        for (int j = 0; j < NPED; j++) {
            if (j == tid) continue;
            float dx = xs[j] - xi;
            float dy = ys[j] - yi;
            int cx = (int)floorf((dx + WBH)/WB*4.0f);
            int cy = (int)floorf((dy + HBH)/HBv*4.0f);
            if (cx >= 0 && cx < 4 && cy >= 0 && cy < 4) {
                int cell = cx + cy*4;
                int pos = atomicAdd(&scnt[cell], 1);
                if (pos < CAP) d_pairs[(t*GG + cell)*CAP + pos] = (tid << 8) | j;
            }
        }
        float* iep = d_ie + (t*NPED + tid)*EMB;
        #pragma unroll 8
        for (int e = 0; e < EMB; e++) {
            float v = fmaf(W_emb[2*e], xi, fmaf(W_emb[2*e+1], yi, b_emb[e]));
            iep[e] = fmaxf(v, 0.f);
        }
        __syncthreads();
        if (tid < GG) d_pcnt[t*GG + tid] = min(scnt[tid], CAP);
    }

    // ---- load persistent B_s = [W_ih | W_hh] slice for this CTA's 64 gate-cols ----
    const int rowt = b >> 3, rt = b & 7;
    const int n0 = rowt*16, r0 = rt*16;
    for (int idx = tid; idx < 64*KDIM; idx += TPB) {
        int ql = idx >> 8, k = idx & 255;
        int q = (ql >> 4)*RNN + r0 + (ql & 15);
        B_s[ql*BSTR + k] = (k < RNN) ? W_ih[q*RNN + k] : W_hh[q*RNN + (k - RNN)];
    }
    if (tid < EMB) bt_s[tid] = b_tens[tid];

    gbar(&lsense);   // barrier #1: precompute done

    const int ks   = tid & 3;       // K-slice (split-K=4)
    const int slot = tid >> 2;
    const int row4 = slot >> 4;     // 4-row group
    const int q4   = slot & 15;     // 4-col group
    const int gc   = b >> 3, sub = b & 7;

    for (int t = 0; t < TSEQ; t++) {
        const int pt = t & 1, pn = pt ^ 1;

        // ---- stage A panel: [ie_t | relu(te+b_tens) | h] for 16 rows ----
        {
            const float* iet = d_ie + t*NPED*EMB;
            const float* tep = d_te[pt];
            const float* hp  = d_h[pt];
            const int k = tid;
            #pragma unroll
            for (int m = 0; m < 16; m++) {
                const int n = n0 + m;
                float v;
                if (k < 64)       v = iet[n*EMB + k];
                else if (k < 128) v = fmaxf(tep[n*EMB + (k-64)] + bt_s[k-64], 0.f);
                else              v = hp[n*RNN + (k-128)];
                A_s[m*ASTR + k] = v;
            }
        }
        __syncthreads();

        // ---- gates GEMM: 16 rows x 64 cols, K=256, split-K=4, 4x4 reg tile ----
        float acc[4][4];
        #pragma unroll
        for (int i = 0; i < 4; i++)
            #pragma unroll
            for (int j = 0; j < 4; j++) acc[i][j] = 0.f;
        {
            const float* Ab = A_s + (row4*4)*ASTR + ks*64;
            const float* Bb = B_s + (q4*4)*BSTR + ks*64;
            #pragma unroll 4
            for (int kk = 0; kk < 64; kk += 4) {
                float4 av[4], bv[4];
                #pragma unroll
                for (int i = 0; i < 4; i++) av[i] = *(const float4*)(Ab + i*ASTR + kk);
                #pragma unroll
                for (int j = 0; j < 4; j++) bv[j] = *(const float4*)(Bb + j*BSTR + kk);
                #pragma unroll
                for (int i = 0; i < 4; i++)
                    #pragma unroll
                    for (int j = 0; j < 4; j++) {
                        acc[i][j] = fmaf(av[i].x, bv[j].x, acc[i][j]);
                        acc[i][j] = fmaf(av[i].y, bv[j].y, acc[i][j]);
                        acc[i][j] = fmaf(av[i].z, bv[j].z, acc[i][j]);
                        acc[i][j] = fmaf(av[i].w, bv[j].w, acc[i][j]);
                    }
            }
        }
        #pragma unroll
        for (int i = 0; i < 4; i++)
            #pragma unroll
            for (int j = 0; j < 4; j++) {
                float v = acc[i][j];
                v += __shfl_xor_sync(0xffffffffu, v, 1);
                v += __shfl_xor_sync(0xffffffffu, v, 2);
                acc[i][j] = v;
            }
        if (ks == 0) {
            #pragma unroll
            for (int i = 0; i < 4; i++)
                #pragma unroll
                for (int j = 0; j < 4; j++)
                    G_s[(row4*4+i)*GSTR + q4*4 + j] = acc[i][j];
        }
        __syncthreads();

        // ---- LSTM pointwise: each thread owns one (n, r) ----
        {
            const int rl = tid >> 4, rr = tid & 15;
            const int n = n0 + rl, r = r0 + rr;
            const float* gs = G_s + rl*GSTR + rr;
            float gi = gs[0]  + b_ih[r]         + b_hh[r];
            float gf = gs[16] + b_ih[RNN+r]     + b_hh[RNN+r];
            float gg = gs[32] + b_ih[2*RNN+r]   + b_hh[2*RNN+r];
            float go = gs[48] + b_ih[3*RNN+r]   + b_hh[3*RNN+r];
            float co = d_c[n*RNN + r];
            float si = 1.f/(1.f + expf(-gi));
            float sf = 1.f/(1.f + expf(-gf));
            float so = 1.f/(1.f + expf(-go));
            float cn = sf*co + si*tanhf(gg);
            d_c[n*RNN + r] = cn;
            d_h[pn][n*RNN + r] = so*tanhf(cn);
        }
        gbar(&lsense);   // h_{t+1} ready everywhere

        // ---- zero te[pt] (to be re-accumulated for step t+2) ----
        if (gt < NPED*EMB) d_te[pt][gt] = 0.f;

        // ---- output projection for step t: peds 2b, 2b+1 ----
        {
            if (tid < 2*OUTD) o_s[tid] = 0.f;
            __syncthreads();
            const int pp = tid >> 7, r = tid & 127;
            const int n = 2*b + pp;
            const float hv = d_h[pn][n*RNN + r];
            #pragma unroll
            for (int o = 0; o < OUTD; o++) {
                float pv = hv * W_out[o*RNN + r];
                pv += __shfl_down_sync(0xffffffffu, pv, 16);
                pv += __shfl_down_sync(0xffffffffu, pv, 8);
                pv += __shfl_down_sync(0xffffffffu, pv, 4);
                pv += __shfl_down_sync(0xffffffffu, pv, 2);
                pv += __shfl_down_sync(0xffffffffu, pv, 1);
                if ((tid & 31) == 0) atomicAdd(&o_s[pp*OUTD + o], pv);
            }
            __syncthreads();
            if (tid < 2*OUTD)
                out[(t*NPED + 2*b + tid/OUTD)*OUTD + (tid % OUTD)] = o_s[tid] + b_out[tid % OUTD];
        }

        // ---- sparse social accumulation for step t+1 (cell gc, stripe sub) ----
        if (t < TSEQ-1) {
            const int tn = t+1;
            const int cnt = d_pcnt[tn*GG + gc];
            const int* pl = d_pairs + (tn*GG + gc)*CAP;
            for (int p = sub; p < cnt; p += 8) {
                const int pr = pl[p];
                const int i = pr >> 8, j = pr & 255;
                __syncthreads();
                if (tid < RNN) h_s[tid] = d_h[pn][j*RNN + tid];
                __syncthreads();
                const float* hh = h_s + (tid & 3)*32;
                float s = 0.f;
                #pragma unroll
                for (int r = 0; r < 32; r++) s = fmaf(wreg[r], hh[r], s);
                s += __shfl_xor_sync(0xffffffffu, s, 1);
                s += __shfl_xor_sync(0xffffffffu, s, 2);
                if ((tid & 3) == 0) atomicAdd(&d_te[pn][i*EMB + (tid >> 2)], s);
            }
        }
        gbar(&lsense);   // te_{t+1} ready
    }
    gbar(&lsense);  // dummy: total barriers = 1 + 2*128 + 1 = 258 (even -> state returns to 0)

    // ---- epilogue: hT, cT (final h lives in buffer 0) ----
    {
        float* hT = out + TSEQ*NPED*OUTD;
        float* cT = hT + NPED*RNN;
        hT[gt] = d_h[0][gt];
        cT[gt] = d_c[gt];
    }
}

extern "C" void kernel_launch(void* const* d_in, const int* in_sizes, int n_in,
                              void* d_out, int out_size) {
    const float* V      = (const float*)d_in[0];
    // d_in[1] = PedsList (identity arange) -- unused by construction
    const float* W_emb  = (const float*)d_in[2];
    const float* b_emb  = (const float*)d_in[3];
    const float* W_tens = (const float*)d_in[4];
    const float* b_tens = (const float*)d_in[5];
    const float* W_ih   = (const float*)d_in[6];
    const float* b_ih   = (const float*)d_in[7];
    const float* W_hh   = (const float*)d_in[8];
    const float* b_hh   = (const float*)d_in[9];
    const float* W_out  = (const float*)d_in[10];
    const float* b_out  = (const float*)d_in[11];
    float* out = (float*)d_out;

    const int smem_bytes = (64*BSTR + 16*ASTR + 16*GSTR + 128 + 64 + 16) * (int)sizeof(float); // 88384
    cudaFuncSetAttribute(social_kernel, cudaFuncAttributeMaxDynamicSharedMemorySize, smem_bytes);
    social_kernel<<<NCTA, TPB, smem_bytes>>>(V, W_emb, b_emb, W_tens, b_tens,
                                             W_ih, b_ih, W_hh, b_hh, W_out, b_out, out);
}

// round 4
// speedup vs baseline: 1.3266x; 1.3266x over previous
#include <cuda_runtime.h>
#include <math.h>

#define TSEQ 128
#define NPED 256
#define RNN  128
#define EMB  64
#define GG   16
#define OUTD 5
#define NCTA 128
#define TPB  256
#define CAP2 256
#define KDIM 256
#define ASTR 260
#define BSTR 260
#define GSTR 68

// ---- persistent device scratch (no allocations allowed) ----
__device__ float d_h[2][NPED*RNN];            // double-buffered hidden state
__device__ float d_te_all[TSEQ*NPED*EMB];     // per-step social accumulators (pre-bias), zeroed once
__device__ float d_ie[TSEQ*NPED*EMB];         // precomputed input embeddings
__device__ int   d_pairs2[TSEQ*GG*CAP2];      // pair lists bucketed by (t, rowgroup(j)): (i<<8)|(jl<<4)|cell
__device__ int   d_pcnt2[TSEQ*GG];
__device__ volatile int d_sense;              // grid barrier (even total flips -> returns to 0)
__device__ int d_count;

__device__ __forceinline__ void gbar(int* lsense) {
    __syncthreads();
    if (threadIdx.x == 0) {
        int s = 1 - *lsense;
        *lsense = s;
        __threadfence();
        int arrived = atomicAdd(&d_count, 1);
        if (arrived == NCTA - 1) {
            d_count = 0;
            __threadfence();
            d_sense = s;
        } else {
            while (d_sense != s) { }
        }
        __threadfence();
    }
    __syncthreads();
}

__global__ void __launch_bounds__(TPB, 1)
social_kernel(const float* __restrict__ V,
              const float* __restrict__ W_emb, const float* __restrict__ b_emb,
              const float* __restrict__ W_tens, const float* __restrict__ b_tens,
              const float* __restrict__ W_ih,  const float* __restrict__ b_ih,
              const float* __restrict__ W_hh,  const float* __restrict__ b_hh,
              const float* __restrict__ W_out, const float* __restrict__ b_out,
              float* __restrict__ out)
{
    extern __shared__ float sm[];
    float* B_s   = sm;                      // 64 x BSTR : persistent [W_ih|W_hh] column slice
    float* Wt_s  = B_s  + 64*BSTR;          // 16*16*64  : W_tens[cell][rl][e] for this CTA's r-slice
    float* A_s   = Wt_s + GG*16*64;         // 16 x ASTR : per-step A panel [ie|relu(te+b)|h]
    float* G_s   = A_s  + 16*ASTR;          // 16 x GSTR : gates tile
    float* h_tile= G_s  + 16*GSTR;          // 16 x 17   : local h[n0:16][r0:16] tile
    float* bt_s  = h_tile + 16*17;          // 64        : b_tens
    float* Wout_s= bt_s + 64;               // 80        : W_out[o][r0:r0+16]
    __shared__ int pl_s[CAP2];
    __shared__ int scnt2[GG];
    __shared__ int lsense;

    const int tid = threadIdx.x;
    const int b   = blockIdx.x;
    const int gt  = b*TPB + tid;

    if (tid == 0) lsense = 0;

    const int rowt = b >> 3, rt = b & 7;
    const int n0 = rowt*16, r0 = rt*16;
    const int nl = tid >> 4, rl = tid & 15;
    const int n  = n0 + nl,  r  = r0 + rl;

    // ---- zero recurrent state; zero this CTA's slice of d_te_all; init out with bias ----
    d_h[0][gt] = 0.f;
    {
        float* tz = d_te_all + b*(TSEQ*NPED*EMB/NCTA);
        #pragma unroll
        for (int k = tid; k < TSEQ*NPED*EMB/NCTA; k += TPB) tz[k] = 0.f;
        // out init: TSEQ*NPED*OUTD = 163840 = 128 * 1280
        float* oz = out + b*1280;
        #pragma unroll
        for (int k = tid; k < 1280; k += TPB) oz[k] = b_out[k % OUTD];
    }

    // ---- precompute for frame t=b: positions, pair buckets by rowgroup(j), ie ----
    {
        const int t = b;
        float* xs = A_s;            // scratch reuse
        float* ys = A_s + NPED;
        xs[tid] = V[t*NPED + tid];
        ys[tid] = V[TSEQ*NPED + t*NPED + tid];
        if (tid < GG) scnt2[tid] = 0;
        __syncthreads();
        const float WB  = (float)(64.0/720.0), WBH = (float)(32.0/720.0);
        const float HBv = (float)(64.0/576.0), HBH = (float)(32.0/576.0);
        const float xi = xs[tid], yi = ys[tid];
        const int i = tid;
        for (int j = 0; j < NPED; j++) {
            if (j == i) continue;
            float dx = xs[j] - xi;
            float dy = ys[j] - yi;
            int cx = (int)floorf((dx + WBH)/WB*4.0f);
            int cy = (int)floorf((dy + HBH)/HBv*4.0f);
            if (cx >= 0 && cx < 4 && cy >= 0 && cy < 4) {
                int cell = cx + cy*4;
                int rj = j >> 4;
                int pos = atomicAdd(&scnt2[rj], 1);
                if (pos < CAP2)
                    d_pairs2[(t*GG + rj)*CAP2 + pos] = (i << 8) | ((j & 15) << 4) | cell;
            }
        }
        float* iep = d_ie + (t*NPED + i)*EMB;
        #pragma unroll 8
        for (int e = 0; e < EMB; e++) {
            float v = fmaf(W_emb[2*e], xi, fmaf(W_emb[2*e+1], yi, b_emb[e]));
            iep[e] = fmaxf(v, 0.f);
        }
        __syncthreads();
        if (tid < GG) d_pcnt2[t*GG + tid] = min(scnt2[tid], CAP2);
    }

    // ---- persistent smem weights ----
    for (int idx = tid; idx < 64*KDIM; idx += TPB) {
        int ql = idx >> 8, k = idx & 255;
        int q = (ql >> 4)*RNN + r0 + (ql & 15);
        B_s[ql*BSTR + k] = (k < RNN) ? W_ih[q*RNN + k] : W_hh[q*RNN + (k - RNN)];
    }
    for (int idx = tid; idx < GG*16*64; idx += TPB) {
        int e = idx & 63, rr = (idx >> 6) & 15, cell = idx >> 10;
        Wt_s[idx] = W_tens[e*(GG*RNN) + cell*RNN + r0 + rr];   // layout [cell][rl][e]
    }
    if (tid < EMB) bt_s[tid] = b_tens[tid];
    if (tid < OUTD*16) Wout_s[tid] = W_out[(tid >> 4)*RNN + r0 + (tid & 15)];

    // ---- per-thread recurrent registers: gate biases + cell state ----
    const float bi = b_ih[r]         + b_hh[r];
    const float bf = b_ih[RNN+r]     + b_hh[RNN+r];
    const float bg = b_ih[2*RNN+r]   + b_hh[2*RNN+r];
    const float bo = b_ih[3*RNN+r]   + b_hh[3*RNN+r];
    float creg = 0.f;

    gbar(&lsense);   // barrier #1: precompute done

    const int ks   = tid & 3;       // split-K=4
    const int slot = tid >> 2;
    const int row4 = slot >> 4;
    const int q4   = slot & 15;

    for (int t = 0; t < TSEQ; t++) {
        const int pt = t & 1, pn = pt ^ 1;

        // ---- stage A panel: [ie_t | relu(te_t + b_tens) | h_t] ----
        {
            const float* iet = d_ie + t*NPED*EMB;
            const float* tep = d_te_all + t*NPED*EMB;
            const float* hp  = d_h[pt];
            const int k = tid;
            #pragma unroll
            for (int m = 0; m < 16; m++) {
                const int nn = n0 + m;
                float v;
                if (k < 64)       v = iet[nn*EMB + k];
                else if (k < 128) v = fmaxf(tep[nn*EMB + (k-64)] + bt_s[k-64], 0.f);
                else              v = hp[nn*RNN + (k-128)];
                A_s[m*ASTR + k] = v;
            }
        }
        // ---- prefetch next-step pair list into smem (h-independent) ----
        int cnt = 0;
        if (t < TSEQ-1) {
            cnt = d_pcnt2[(t+1)*GG + rowt];
            if (tid < cnt) pl_s[tid] = d_pairs2[((t+1)*GG + rowt)*CAP2 + tid];
        }
        __syncthreads();

        // ---- gates GEMM: 16 x 64, K=256, split-K=4, 4x4 reg tile ----
        float acc[4][4];
        #pragma unroll
        for (int i = 0; i < 4; i++)
            #pragma unroll
            for (int j = 0; j < 4; j++) acc[i][j] = 0.f;
        {
            const float* Ab = A_s + (row4*4)*ASTR + ks*64;
            const float* Bb = B_s + (q4*4)*BSTR + ks*64;
            #pragma unroll 4
            for (int kk = 0; kk < 64; kk += 4) {
                float4 av[4], bv[4];
                #pragma unroll
                for (int i = 0; i < 4; i++) av[i] = *(const float4*)(Ab + i*ASTR + kk);
                #pragma unroll
                for (int j = 0; j < 4; j++) bv[j] = *(const float4*)(Bb + j*BSTR + kk);
                #pragma unroll
                for (int i = 0; i < 4; i++)
                    #pragma unroll
                    for (int j = 0; j < 4; j++) {
                        acc[i][j] = fmaf(av[i].x, bv[j].x, acc[i][j]);
                        acc[i][j] = fmaf(av[i].y, bv[j].y, acc[i][j]);
                        acc[i][j] = fmaf(av[i].z, bv[j].z, acc[i][j]);
                        acc[i][j] = fmaf(av[i].w, bv[j].w, acc[i][j]);
                    }
            }
        }
        #pragma unroll
        for (int i = 0; i < 4; i++)
            #pragma unroll
            for (int j = 0; j < 4; j++) {
                float v = acc[i][j];
                v += __shfl_xor_sync(0xffffffffu, v, 1);
                v += __shfl_xor_sync(0xffffffffu, v, 2);
                acc[i][j] = v;
            }
        if (ks == 0) {
            #pragma unroll
            for (int i = 0; i < 4; i++)
                #pragma unroll
                for (int j = 0; j < 4; j++)
                    G_s[(row4*4+i)*GSTR + q4*4 + j] = acc[i][j];
        }
        __syncthreads();

        // ---- LSTM pointwise + output projection (all local) ----
        {
            const float* gs = G_s + nl*GSTR + rl;
            float gi = gs[0]  + bi;
            float gf = gs[16] + bf;
            float gg = gs[32] + bg;
            float go = gs[48] + bo;
            float si = 1.f/(1.f + expf(-gi));
            float sf = 1.f/(1.f + expf(-gf));
            float so = 1.f/(1.f + expf(-go));
            creg = sf*creg + si*tanhf(gg);
            float hv = so*tanhf(creg);
            h_tile[nl*17 + rl] = hv;
            d_h[pn][n*RNN + r] = hv;

            #pragma unroll
            for (int o = 0; o < OUTD; o++) {
                float pv = hv * Wout_s[o*16 + rl];
                pv += __shfl_xor_sync(0xffffffffu, pv, 8);
                pv += __shfl_xor_sync(0xffffffffu, pv, 4);
                pv += __shfl_xor_sync(0xffffffffu, pv, 2);
                pv += __shfl_xor_sync(0xffffffffu, pv, 1);
                if (rl == 0) atomicAdd(out + (t*NPED + n)*OUTD + o, pv);
            }
        }
        __syncthreads();

        // ---- social partial sums for step t+1: j in my rowgroup, r in my slice ----
        if (t < TSEQ-1) {
            float* tew = d_te_all + (t+1)*NPED*EMB;
            const int grp = tid >> 6;   // 4 pair-groups of 64 threads
            const int e   = tid & 63;
            for (int p = grp; p < cnt; p += 4) {
                const int pr = pl_s[p];
                const int i  = pr >> 8, jl = (pr >> 4) & 15, cell = pr & 15;
                const float* wt = Wt_s + cell*(16*64) + e;
                const float* hh = h_tile + jl*17;
                float s = 0.f;
                #pragma unroll
                for (int rr = 0; rr < 16; rr++) s = fmaf(wt[rr*64], hh[rr], s);
                atomicAdd(tew + i*EMB + e, s);
            }
        }

        gbar(&lsense);   // single barrier: h_{t+1} + te_{t+1} ready everywhere
    }
    gbar(&lsense);  // dummy: total barriers = 1 + 128 + 1 = 130 (even -> sense returns to 0)

    // ---- epilogue: hT (in d_h[0] after t=127), cT from registers ----
    {
        float* hT = out + TSEQ*NPED*OUTD;
        float* cT = hT + NPED*RNN;
        hT[gt] = d_h[0][gt];
        cT[n*RNN + r] = creg;
    }
}

extern "C" void kernel_launch(void* const* d_in, const int* in_sizes, int n_in,
                              void* d_out, int out_size) {
    const float* V      = (const float*)d_in[0];
    // d_in[1] = PedsList (identity arange) -- unused by construction
    const float* W_emb  = (const float*)d_in[2];
    const float* b_emb  = (const float*)d_in[3];
    const float* W_tens = (const float*)d_in[4];
    const float* b_tens = (const float*)d_in[5];
    const float* W_ih   = (const float*)d_in[6];
    const float* b_ih   = (const float*)d_in[7];
    const float* W_hh   = (const float*)d_in[8];
    const float* b_hh   = (const float*)d_in[9];
    const float* W_out  = (const float*)d_in[10];
    const float* b_out  = (const float*)d_in[11];
    float* out = (float*)d_out;

    const int smem_bytes = (64*BSTR + GG*16*64 + 16*ASTR + 16*GSTR + 16*17 + 64 + 80)
                           * (int)sizeof(float); // 154,752 B
    cudaFuncSetAttribute(social_kernel, cudaFuncAttributeMaxDynamicSharedMemorySize, smem_bytes);
    social_kernel<<<NCTA, TPB, smem_bytes>>>(V, W_emb, b_emb, W_tens, b_tens,
                                             W_ih, b_ih, W_hh, b_hh, W_out, b_out, out);
}

// round 5
// speedup vs baseline: 1.7666x; 1.3317x over previous
#include <cuda_runtime.h>
#include <math.h>

#define TSEQ 128
#define NPED 256
#define RNN  128
#define EMB  64
#define GG   16
#define OUTD 5
#define NCTA 128
#define TPB  256
#define CAP2 256
#define KDIM 256
#define ASTR 260
#define BSTR 260
#define GSTR 68

// ---- persistent device scratch (no allocations allowed) ----
__device__ float d_h[2][NPED*RNN];            // double-buffered hidden state
__device__ float d_te_all[TSEQ*NPED*EMB];     // per-step social accumulators (pre-bias), zeroed once
__device__ float d_ie[TSEQ*NPED*EMB];         // precomputed input embeddings
__device__ int   d_pairs2[TSEQ*GG*CAP2];      // pair lists bucketed by (t, rowgroup(j)): (i<<8)|(jl<<4)|cell
__device__ int   d_pcnt2[TSEQ*GG];
__device__ int   d_cnt_l[8];                  // 2-level barrier: per-group arrival counts
__device__ int   d_cnt_r;                     // root arrival count
__device__ volatile int d_sense;              // barrier sense (130 flips/launch -> returns to 0)

__device__ __forceinline__ void gbar(int* lsense, int grp) {
    __syncthreads();
    if (threadIdx.x == 0) {
        int s = 1 - *lsense;
        *lsense = s;
        __threadfence();                       // release my writes
        if (atomicAdd(&d_cnt_l[grp], 1) == 15) {
            d_cnt_l[grp] = 0;
            __threadfence();                   // reset visible before root arrive
            if (atomicAdd(&d_cnt_r, 1) == 7) {
                d_cnt_r = 0;
                __threadfence();               // reset visible before release
                d_sense = s;
            }
        }
        while (d_sense != s) { }
        __threadfence();                       // acquire
    }
    __syncthreads();
}

__device__ __forceinline__ float sigf(float x) {
    return __fdividef(1.f, 1.f + __expf(-x));
}
__device__ __forceinline__ float tanhfast(float x) {
    x = fminf(fmaxf(x, -15.f), 15.f);
    float e = __expf(2.f * x);
    return __fdividef(e - 1.f, e + 1.f);
}

__global__ void __launch_bounds__(TPB, 1)
social_kernel(const float* __restrict__ V,
              const float* __restrict__ W_emb, const float* __restrict__ b_emb,
              const float* __restrict__ W_tens, const float* __restrict__ b_tens,
              const float* __restrict__ W_ih,  const float* __restrict__ b_ih,
              const float* __restrict__ W_hh,  const float* __restrict__ b_hh,
              const float* __restrict__ W_out, const float* __restrict__ b_out,
              float* __restrict__ out)
{
    extern __shared__ float sm[];
    float* B_s   = sm;                      // 64 x BSTR : persistent [W_ih|W_hh] column slice
    float* Wt_s  = B_s  + 64*BSTR;          // 16*16*64  : W_tens[cell][rl][e] for this CTA's r-slice
    float* A_s   = Wt_s + GG*16*64;         // 16 x ASTR : per-step A panel [ie|relu(te+b)|h]
    float* G_s   = A_s  + 16*ASTR;          // 16 x GSTR : gates tile
    float* h_tile= G_s  + 16*GSTR;          // 16 x 17   : local h[n0:16][r0:16] tile
    float* bt_s  = h_tile + 16*17;          // 64        : b_tens
    float* Wout_s= bt_s + 64;               // 80        : W_out[o][r0:r0+16]
    __shared__ int pl_s[CAP2];
    __shared__ int scnt2[GG];
    __shared__ int lsense;

    const int tid = threadIdx.x;
    const int b   = blockIdx.x;
    const int gt  = b*TPB + tid;
    const int grp = b >> 4;

    if (tid == 0) lsense = 0;

    const int rowt = b >> 3, rt = b & 7;
    const int n0 = rowt*16, r0 = rt*16;
    const int nl = tid >> 4, rl = tid & 15;
    const int n  = n0 + nl,  r  = r0 + rl;

    // ---- zero recurrent state; zero this CTA's slice of d_te_all; init out with bias ----
    d_h[0][gt] = 0.f;
    {
        float* tz = d_te_all + b*(TSEQ*NPED*EMB/NCTA);
        #pragma unroll
        for (int k = tid; k < TSEQ*NPED*EMB/NCTA; k += TPB) tz[k] = 0.f;
        float* oz = out + b*1280;   // TSEQ*NPED*OUTD = 128*1280
        #pragma unroll
        for (int k = tid; k < 1280; k += TPB) oz[k] = b_out[k % OUTD];
    }

    // ---- precompute for frame t=b: positions, pair buckets by rowgroup(j), ie ----
    {
        const int t = b;
        float* xs = A_s;            // scratch reuse
        float* ys = A_s + NPED;
        xs[tid] = V[t*NPED + tid];
        ys[tid] = V[TSEQ*NPED + t*NPED + tid];
        if (tid < GG) scnt2[tid] = 0;
        __syncthreads();
        const float WB  = (float)(64.0/720.0), WBH = (float)(32.0/720.0);
        const float HBv = (float)(64.0/576.0), HBH = (float)(32.0/576.0);
        const float xi = xs[tid], yi = ys[tid];
        const int i = tid;
        for (int j = 0; j < NPED; j++) {
            if (j == i) continue;
            float dx = xs[j] - xi;
            float dy = ys[j] - yi;
            int cx = (int)floorf((dx + WBH)/WB*4.0f);
            int cy = (int)floorf((dy + HBH)/HBv*4.0f);
            if (cx >= 0 && cx < 4 && cy >= 0 && cy < 4) {
                int cell = cx + cy*4;
                int rj = j >> 4;
                int pos = atomicAdd(&scnt2[rj], 1);
                if (pos < CAP2)
                    d_pairs2[(t*GG + rj)*CAP2 + pos] = (i << 8) | ((j & 15) << 4) | cell;
            }
        }
        float* iep = d_ie + (t*NPED + i)*EMB;
        #pragma unroll 8
        for (int e = 0; e < EMB; e++) {
            float v = fmaf(W_emb[2*e], xi, fmaf(W_emb[2*e+1], yi, b_emb[e]));
            iep[e] = fmaxf(v, 0.f);
        }
        __syncthreads();
        if (tid < GG) d_pcnt2[t*GG + tid] = min(scnt2[tid], CAP2);
    }

    // ---- persistent smem weights ----
    for (int idx = tid; idx < 64*KDIM; idx += TPB) {
        int ql = idx >> 8, k = idx & 255;
        int q = (ql >> 4)*RNN + r0 + (ql & 15);
        B_s[ql*BSTR + k] = (k < RNN) ? W_ih[q*RNN + k] : W_hh[q*RNN + (k - RNN)];
    }
    for (int idx = tid; idx < GG*16*64; idx += TPB) {
        int e = idx & 63, rr = (idx >> 6) & 15, cell = idx >> 10;
        Wt_s[idx] = W_tens[e*(GG*RNN) + cell*RNN + r0 + rr];   // layout [cell][rl][e]
    }
    if (tid < EMB) bt_s[tid] = b_tens[tid];
    if (tid < OUTD*16) Wout_s[tid] = W_out[(tid >> 4)*RNN + r0 + (tid & 15)];

    // ---- per-thread recurrent registers: gate biases + cell state ----
    const float bi = b_ih[r]         + b_hh[r];
    const float bf = b_ih[RNN+r]     + b_hh[RNN+r];
    const float bg = b_ih[2*RNN+r]   + b_hh[2*RNN+r];
    const float bo = b_ih[3*RNN+r]   + b_hh[3*RNN+r];
    float creg = 0.f;

    gbar(&lsense, grp);   // barrier #1: precompute done

    const int ks   = tid & 3;       // split-K=4, INTERLEAVED slices (conflict-free)
    const int slot = tid >> 2;
    const int row4 = slot >> 4;
    const int q4   = slot & 15;

    for (int t = 0; t < TSEQ; t++) {
        const int pt = t & 1, pn = pt ^ 1;

        // ---- stage A panel: [ie_t | relu(te_t + b_tens) | h_t] ----
        {
            const float* iet = d_ie + t*NPED*EMB;
            const float* tep = d_te_all + t*NPED*EMB;
            const float* hp  = d_h[pt];
            const int k = tid;
            #pragma unroll
            for (int m = 0; m < 16; m++) {
                const int nn = n0 + m;
                float v;
                if (k < 64)       v = iet[nn*EMB + k];
                else if (k < 128) v = fmaxf(tep[nn*EMB + (k-64)] + bt_s[k-64], 0.f);
                else              v = hp[nn*RNN + (k-128)];
                A_s[m*ASTR + k] = v;
            }
        }
        // ---- prefetch next-step pair list into smem (h-independent) ----
        int cnt = 0;
        if (t < TSEQ-1) {
            cnt = d_pcnt2[(t+1)*GG + rowt];
            if (tid < cnt) pl_s[tid] = d_pairs2[((t+1)*GG + rowt)*CAP2 + tid];
        }
        __syncthreads();

        // ---- gates GEMM: 16 x 64, K=256, interleaved split-K=4, 4x4 reg tile ----
        float acc[4][4];
        #pragma unroll
        for (int i = 0; i < 4; i++)
            #pragma unroll
            for (int j = 0; j < 4; j++) acc[i][j] = 0.f;
        {
            // k = ks*4 + u*16 + {0..3}: consecutive 16B chunks per quarter-warp,
            // bank starts cover all 32 banks exactly once -> conflict-free LDS.128
            const float* Ab = A_s + (row4*4)*ASTR + ks*4;
            const float* Bb = B_s + (q4*4)*BSTR + ks*4;
            #pragma unroll 4
            for (int u = 0; u < 16; u++) {
                float4 av[4], bv[4];
                #pragma unroll
                for (int i = 0; i < 4; i++) av[i] = *(const float4*)(Ab + i*ASTR + u*16);
                #pragma unroll
                for (int j = 0; j < 4; j++) bv[j] = *(const float4*)(Bb + j*BSTR + u*16);
                #pragma unroll
                for (int i = 0; i < 4; i++)
                    #pragma unroll
                    for (int j = 0; j < 4; j++) {
                        acc[i][j] = fmaf(av[i].x, bv[j].x, acc[i][j]);
                        acc[i][j] = fmaf(av[i].y, bv[j].y, acc[i][j]);
                        acc[i][j] = fmaf(av[i].z, bv[j].z, acc[i][j]);
                        acc[i][j] = fmaf(av[i].w, bv[j].w, acc[i][j]);
                    }
            }
        }
        #pragma unroll
        for (int i = 0; i < 4; i++)
            #pragma unroll
            for (int j = 0; j < 4; j++) {
                float v = acc[i][j];
                v += __shfl_xor_sync(0xffffffffu, v, 1);
                v += __shfl_xor_sync(0xffffffffu, v, 2);
                acc[i][j] = v;
            }
        if (ks == 0) {
            #pragma unroll
            for (int i = 0; i < 4; i++)
                #pragma unroll
                for (int j = 0; j < 4; j++)
                    G_s[(row4*4+i)*GSTR + q4*4 + j] = acc[i][j];
        }
        __syncthreads();

        // ---- LSTM pointwise + output projection (all local) ----
        {
            const float* gs = G_s + nl*GSTR + rl;
            float gi = gs[0]  + bi;
            float gf = gs[16] + bf;
            float gg = gs[32] + bg;
            float go = gs[48] + bo;
            float si = sigf(gi);
            float sf = sigf(gf);
            float so = sigf(go);
            creg = sf*creg + si*tanhfast(gg);
            float hv = so*tanhfast(creg);
            h_tile[nl*17 + rl] = hv;
            d_h[pn][n*RNN + r] = hv;

            #pragma unroll
            for (int o = 0; o < OUTD; o++) {
                float pv = hv * Wout_s[o*16 + rl];
                pv += __shfl_xor_sync(0xffffffffu, pv, 8);
                pv += __shfl_xor_sync(0xffffffffu, pv, 4);
                pv += __shfl_xor_sync(0xffffffffu, pv, 2);
                pv += __shfl_xor_sync(0xffffffffu, pv, 1);
                if (rl == 0) atomicAdd(out + (t*NPED + n)*OUTD + o, pv);
            }
        }
        __syncthreads();

        // ---- social partial sums for step t+1: j in my rowgroup, r in my slice ----
        if (t < TSEQ-1) {
            float* tew = d_te_all + (t+1)*NPED*EMB;
            const int pg = tid >> 6;   // 4 pair-groups of 64 threads
            const int e  = tid & 63;
            for (int p = pg; p < cnt; p += 4) {
                const int pr = pl_s[p];
                const int i  = pr >> 8, jl = (pr >> 4) & 15, cell = pr & 15;
                const float* wt = Wt_s + cell*(16*64) + e;
                const float* hh = h_tile + jl*17;
                float s = 0.f;
                #pragma unroll
                for (int rr = 0; rr < 16; rr++) s = fmaf(wt[rr*64], hh[rr], s);
                atomicAdd(tew + i*EMB + e, s);
            }
        }

        gbar(&lsense, grp);   // single barrier: h_{t+1} + te_{t+1} ready everywhere
    }
    gbar(&lsense, grp);  // dummy: total barriers = 1 + 128 + 1 = 130 (even -> sense returns to 0)

    // ---- epilogue: hT (in d_h[0] after t=127), cT from registers ----
    {
        float* hT = out + TSEQ*NPED*OUTD;
        float* cT = hT + NPED*RNN;
        hT[gt] = d_h[0][gt];
        cT[n*RNN + r] = creg;
    }
}

extern "C" void kernel_launch(void* const* d_in, const int* in_sizes, int n_in,
                              void* d_out, int out_size) {
    const float* V      = (const float*)d_in[0];
    // d_in[1] = PedsList (identity arange) -- unused by construction
    const float* W_emb  = (const float*)d_in[2];
    const float* b_emb  = (const float*)d_in[3];
    const float* W_tens = (const float*)d_in[4];
    const float* b_tens = (const float*)d_in[5];
    const float* W_ih   = (const float*)d_in[6];
    const float* b_ih   = (const float*)d_in[7];
    const float* W_hh   = (const float*)d_in[8];
    const float* b_hh   = (const float*)d_in[9];
    const float* W_out  = (const float*)d_in[10];
    const float* b_out  = (const float*)d_in[11];
    float* out = (float*)d_out;

    const int smem_bytes = (64*BSTR + GG*16*64 + 16*ASTR + 16*GSTR + 16*17 + 64 + 80)
                           * (int)sizeof(float); // 154,752 B
    cudaFuncSetAttribute(social_kernel, cudaFuncAttributeMaxDynamicSharedMemorySize, smem_bytes);
    social_kernel<<<NCTA, TPB, smem_bytes>>>(V, W_emb, b_emb, W_tens, b_tens,
                                             W_ih, b_ih, W_hh, b_hh, W_out, b_out, out);
}

// round 6
// speedup vs baseline: 2.8994x; 1.6412x over previous
#include <cuda_runtime.h>
#include <math.h>

#define TSEQ 128
#define NPED 256
#define RNN  128
#define EMB  64
#define GG   16
#define OUTD 5
#define NCTA 128
#define TPB  256
#define CAP2 256
#define KDIM 256
#define ASTR 260
#define BSTR 260
#define GSTR 68

// ---- persistent device scratch (no allocations allowed) ----
__device__ float d_h[2][NPED*RNN];            // double-buffered hidden state
__device__ float d_te_all[TSEQ*NPED*EMB];     // per-step social accumulators (pre-bias), zeroed once
__device__ float d_ie[TSEQ*NPED*EMB];         // precomputed input embeddings
__device__ int   d_pairs2[TSEQ*GG*CAP2];      // pair lists bucketed by (t, rowgroup(j)): (i<<8)|(jl<<4)|cell
__device__ int   d_pcnt2[TSEQ*GG];
__device__ int   d_cnt_l[8];                  // sense barrier: per-group arrival counts
__device__ int   d_cnt_r;                     // sense barrier: root count
__device__ volatile int d_sense;              // sense barrier (2 flips/launch -> returns to 0)
__device__ int   d_cntH[8];                   // monotonic epoch barrier: h ready
__device__ int   d_cntT[8];                   // monotonic epoch barrier: te ready

// full sense-reversal barrier (used twice: after preamble, after main loop)
__device__ __forceinline__ void gbar(int* lsense, int grp) {
    __syncthreads();
    if (threadIdx.x == 0) {
        int s = 1 - *lsense;
        *lsense = s;
        __threadfence();
        if (atomicAdd(&d_cnt_l[grp], 1) == 15) {
            d_cnt_l[grp] = 0;
            __threadfence();
            if (atomicAdd(&d_cnt_r, 1) == 7) {
                d_cnt_r = 0;
                __threadfence();
                d_sense = s;
            }
        }
        while (d_sense != s) { }
        __threadfence();
    }
    __syncthreads();
}

// split-phase monotonic barrier: arrive (no-return REDG) / wait (relaxed spin)
__device__ __forceinline__ void arrive_bar(int* cnt, int grp) {
    __syncthreads();                    // all CTA threads' prior writes done
    if (threadIdx.x == 0) {
        __threadfence();                // make them globally visible
        asm volatile("red.relaxed.gpu.global.add.s32 [%0], 1;"
                     :: "l"(cnt + grp) : "memory");
    }
}
__device__ __forceinline__ void wait_bar(const int* cnt, int target) {
    if (threadIdx.x == 0) {
        int s;
        do {
            s = 0;
            #pragma unroll
            for (int g = 0; g < 8; g++) {
                int v;
                asm volatile("ld.relaxed.gpu.global.s32 %0, [%1];"
                             : "=r"(v) : "l"(cnt + g) : "memory");
                s += v;
            }
        } while (s < target);
        __threadfence();                // acquire
    }
    __syncthreads();
}

__device__ __forceinline__ float sigf(float x) {
    return __fdividef(1.f, 1.f + __expf(-x));
}
__device__ __forceinline__ float tanhfast(float x) {
    x = fminf(fmaxf(x, -15.f), 15.f);
    float e = __expf(2.f * x);
    return __fdividef(e - 1.f, e + 1.f);
}

template<int U0, int U1>
__device__ __forceinline__ void gemm_acc(float (&acc)[4][4], const float* Ab, const float* Bb) {
    #pragma unroll
    for (int u = U0; u < U1; u++) {
        float4 av[4], bv[4];
        #pragma unroll
        for (int i = 0; i < 4; i++) av[i] = *(const float4*)(Ab + i*ASTR + u*16);
        #pragma unroll
        for (int j = 0; j < 4; j++) bv[j] = *(const float4*)(Bb + j*BSTR + u*16);
        #pragma unroll
        for (int i = 0; i < 4; i++)
            #pragma unroll
            for (int j = 0; j < 4; j++) {
                acc[i][j] = fmaf(av[i].x, bv[j].x, acc[i][j]);
                acc[i][j] = fmaf(av[i].y, bv[j].y, acc[i][j]);
                acc[i][j] = fmaf(av[i].z, bv[j].z, acc[i][j]);
                acc[i][j] = fmaf(av[i].w, bv[j].w, acc[i][j]);
            }
    }
}

__global__ void __launch_bounds__(TPB, 1)
social_kernel(const float* __restrict__ V,
              const float* __restrict__ W_emb, const float* __restrict__ b_emb,
              const float* __restrict__ W_tens, const float* __restrict__ b_tens,
              const float* __restrict__ W_ih,  const float* __restrict__ b_ih,
              const float* __restrict__ W_hh,  const float* __restrict__ b_hh,
              const float* __restrict__ W_out, const float* __restrict__ b_out,
              float* __restrict__ out)
{
    extern __shared__ float sm[];
    float* B_s   = sm;                      // 64 x BSTR : persistent [W_ih|W_hh] column slice
    float* Wt_s  = B_s  + 64*BSTR;          // 16*16*64  : W_tens[cell][rl][e] for this CTA's r-slice
    float* A_s   = Wt_s + GG*16*64;         // 16 x ASTR : per-step A panel [ie|relu(te+b)|h]
    float* G_s   = A_s  + 16*ASTR;          // 16 x GSTR : gates tile
    float* h_tile= G_s  + 16*GSTR;          // 16 x 17   : local h[n0:16][r0:16] tile
    float* bt_s  = h_tile + 16*17;          // 64        : b_tens
    float* Wout_s= bt_s + 64;               // 80        : W_out[o][r0:r0+16]
    __shared__ int pl_s[CAP2];
    __shared__ int scnt2[GG];
    __shared__ int lsense;

    const int tid = threadIdx.x;
    const int b   = blockIdx.x;
    const int gt  = b*TPB + tid;
    const int grp = b >> 4;

    if (tid == 0) lsense = 0;

    const int rowt = b >> 3, rt = b & 7;
    const int n0 = rowt*16, r0 = rt*16;
    const int nl = tid >> 4, rl = tid & 15;
    const int n  = n0 + nl,  r  = r0 + rl;

    // ---- zero recurrent state; zero this CTA's slice of d_te_all; init out with bias ----
    d_h[0][gt] = 0.f;
    {
        float* tz = d_te_all + b*(TSEQ*NPED*EMB/NCTA);
        #pragma unroll
        for (int k = tid; k < TSEQ*NPED*EMB/NCTA; k += TPB) tz[k] = 0.f;
        float* oz = out + b*1280;   // TSEQ*NPED*OUTD = 128*1280
        #pragma unroll
        for (int k = tid; k < 1280; k += TPB) oz[k] = b_out[k % OUTD];
    }

    // ---- precompute for frame t=b: positions, pair buckets by rowgroup(j), ie ----
    {
        const int t = b;
        float* xs = A_s;            // scratch reuse
        float* ys = A_s + NPED;
        xs[tid] = V[t*NPED + tid];
        ys[tid] = V[TSEQ*NPED + t*NPED + tid];
        if (tid < GG) scnt2[tid] = 0;
        __syncthreads();
        const float WB  = (float)(64.0/720.0), WBH = (float)(32.0/720.0);
        const float HBv = (float)(64.0/576.0), HBH = (float)(32.0/576.0);
        const float xi = xs[tid], yi = ys[tid];
        const int i = tid;
        for (int j = 0; j < NPED; j++) {
            if (j == i) continue;
            float dx = xs[j] - xi;
            float dy = ys[j] - yi;
            int cx = (int)floorf((dx + WBH)/WB*4.0f);
            int cy = (int)floorf((dy + HBH)/HBv*4.0f);
            if (cx >= 0 && cx < 4 && cy >= 0 && cy < 4) {
                int cell = cx + cy*4;
                int rj = j >> 4;
                int pos = atomicAdd(&scnt2[rj], 1);
                if (pos < CAP2)
                    d_pairs2[(t*GG + rj)*CAP2 + pos] = (i << 8) | ((j & 15) << 4) | cell;
            }
        }
        float* iep = d_ie + (t*NPED + i)*EMB;
        #pragma unroll 8
        for (int e = 0; e < EMB; e++) {
            float v = fmaf(W_emb[2*e], xi, fmaf(W_emb[2*e+1], yi, b_emb[e]));
            iep[e] = fmaxf(v, 0.f);
        }
        __syncthreads();
        if (tid < GG) d_pcnt2[t*GG + tid] = min(scnt2[tid], CAP2);
    }

    // ---- persistent smem weights ----
    for (int idx = tid; idx < 64*KDIM; idx += TPB) {
        int ql = idx >> 8, k = idx & 255;
        int q = (ql >> 4)*RNN + r0 + (ql & 15);
        B_s[ql*BSTR + k] = (k < RNN) ? W_ih[q*RNN + k] : W_hh[q*RNN + (k - RNN)];
    }
    for (int idx = tid; idx < GG*16*64; idx += TPB) {
        int e = idx & 63, rr = (idx >> 6) & 15, cell = idx >> 10;
        Wt_s[idx] = W_tens[e*(GG*RNN) + cell*RNN + r0 + rr];   // layout [cell][rl][e]
    }
    if (tid < EMB) bt_s[tid] = b_tens[tid];
    if (tid < OUTD*16) Wout_s[tid] = W_out[(tid >> 4)*RNN + r0 + (tid & 15)];

    // ---- per-thread recurrent registers: gate biases + cell state ----
    const float bi = b_ih[r]         + b_hh[r];
    const float bf = b_ih[RNN+r]     + b_hh[RNN+r];
    const float bg = b_ih[2*RNN+r]   + b_hh[2*RNN+r];
    const float bo = b_ih[3*RNN+r]   + b_hh[3*RNN+r];
    float creg = 0.f;

    gbar(&lsense, grp);   // full barrier: preamble done (h0, te0, pairs, ie, out-bias visible)

    const int ks   = tid & 3;       // split-K=4, interleaved slices (conflict-free)
    const int slot = tid >> 2;
    const int row4 = slot >> 4;
    const int q4   = slot & 15;

    for (int t = 0; t < TSEQ; t++) {
        const int pt = t & 1, pn = pt ^ 1;

        // ---- (0) h-independent work: pair list for t+1, ie columns of A ----
        int cnt = 0;
        if (t < TSEQ-1) {
            cnt = d_pcnt2[(t+1)*GG + rowt];
            if (tid < cnt) pl_s[tid] = d_pairs2[((t+1)*GG + rowt)*CAP2 + tid];
        }
        if (tid < 64) {
            const float* iet = d_ie + t*NPED*EMB;
            #pragma unroll
            for (int m = 0; m < 16; m++)
                A_s[m*ASTR + tid] = iet[(n0 + m)*EMB + tid];
        }

        // ---- (1) wait for h_t from all CTAs ----
        wait_bar(d_cntH, 128*t);

        // ---- (2) stage h columns ----
        if (tid >= 128) {
            const float* hp = d_h[pt];
            #pragma unroll
            for (int m = 0; m < 16; m++)
                A_s[m*ASTR + tid] = hp[(n0 + m)*RNN + (tid - 128)];
        }
        __syncthreads();

        // ---- (3) GEMM part 1: ie (u 0..3) + h (u 8..15) columns ----
        float acc[4][4];
        #pragma unroll
        for (int i = 0; i < 4; i++)
            #pragma unroll
            for (int j = 0; j < 4; j++) acc[i][j] = 0.f;
        const float* Ab = A_s + (row4*4)*ASTR + ks*4;
        const float* Bb = B_s + (q4*4)*BSTR + ks*4;
        gemm_acc<0,4>(acc, Ab, Bb);
        gemm_acc<8,16>(acc, Ab, Bb);

        // ---- (4) wait for te_t (others' social hid under part 1) ----
        wait_bar(d_cntT, 128*t);

        // ---- (5) stage te columns ----
        if (tid >= 64 && tid < 128) {
            const float* tep = d_te_all + t*NPED*EMB;
            #pragma unroll
            for (int m = 0; m < 16; m++)
                A_s[m*ASTR + tid] = fmaxf(tep[(n0 + m)*EMB + (tid - 64)] + bt_s[tid - 64], 0.f);
        }
        __syncthreads();

        // ---- (6) GEMM part 2: te columns (u 4..7) ----
        gemm_acc<4,8>(acc, Ab, Bb);

        #pragma unroll
        for (int i = 0; i < 4; i++)
            #pragma unroll
            for (int j = 0; j < 4; j++) {
                float v = acc[i][j];
                v += __shfl_xor_sync(0xffffffffu, v, 1);
                v += __shfl_xor_sync(0xffffffffu, v, 2);
                acc[i][j] = v;
            }
        if (ks == 0) {
            #pragma unroll
            for (int i = 0; i < 4; i++)
                #pragma unroll
                for (int j = 0; j < 4; j++)
                    G_s[(row4*4+i)*GSTR + q4*4 + j] = acc[i][j];
        }
        __syncthreads();

        // ---- (7) LSTM pointwise + output projection (all local) ----
        {
            const float* gs = G_s + nl*GSTR + rl;
            float gi = gs[0]  + bi;
            float gf = gs[16] + bf;
            float gg = gs[32] + bg;
            float go = gs[48] + bo;
            float si = sigf(gi);
            float sf = sigf(gf);
            float so = sigf(go);
            creg = sf*creg + si*tanhfast(gg);
            float hv = so*tanhfast(creg);
            h_tile[nl*17 + rl] = hv;
            d_h[pn][n*RNN + r] = hv;

            #pragma unroll
            for (int o = 0; o < OUTD; o++) {
                float pv = hv * Wout_s[o*16 + rl];
                pv += __shfl_xor_sync(0xffffffffu, pv, 8);
                pv += __shfl_xor_sync(0xffffffffu, pv, 4);
                pv += __shfl_xor_sync(0xffffffffu, pv, 2);
                pv += __shfl_xor_sync(0xffffffffu, pv, 1);
                if (rl == 0) atomicAdd(out + (t*NPED + n)*OUTD + o, pv);
            }
        }

        // ---- (8) announce h_{t+1} ----
        arrive_bar(d_cntH, grp);

        // ---- (9) social partial sums for te_{t+1} (local h_tile, off critical path) ----
        if (t < TSEQ-1) {
            float* tew = d_te_all + (t+1)*NPED*EMB;
            const int pg = tid >> 6;   // 4 pair-groups of 64 threads
            const int e  = tid & 63;
            for (int p = pg; p < cnt; p += 4) {
                const int pr = pl_s[p];
                const int i  = pr >> 8, jl = (pr >> 4) & 15, cell = pr & 15;
                const float* wt = Wt_s + cell*(16*64) + e;
                const float* hh = h_tile + jl*17;
                float s = 0.f;
                #pragma unroll
                for (int rr = 0; rr < 16; rr++) s = fmaf(wt[rr*64], hh[rr], s);
                atomicAdd(tew + i*EMB + e, s);
            }
        }

        // ---- (10) announce te_{t+1} ----
        arrive_bar(d_cntT, grp);
    }

    gbar(&lsense, grp);  // full barrier; sense flips total = 2 (returns to 0)

    // reset monotonic counters for the next graph replay
    if (b == 0 && tid < 8) { d_cntH[tid] = 0; d_cntT[tid] = 0; }

    // ---- epilogue: hT (in d_h[0] after t=127), cT from registers ----
    {
        float* hT = out + TSEQ*NPED*OUTD;
        float* cT = hT + NPED*RNN;
        hT[gt] = d_h[0][gt];
        cT[n*RNN + r] = creg;
    }
}

extern "C" void kernel_launch(void* const* d_in, const int* in_sizes, int n_in,
                              void* d_out, int out_size) {
    const float* V      = (const float*)d_in[0];
    // d_in[1] = PedsList (identity arange) -- unused by construction
    const float* W_emb  = (const float*)d_in[2];
    const float* b_emb  = (const float*)d_in[3];
    const float* W_tens = (const float*)d_in[4];
    const float* b_tens = (const float*)d_in[5];
    const float* W_ih   = (const float*)d_in[6];
    const float* b_ih   = (const float*)d_in[7];
    const float* W_hh   = (const float*)d_in[8];
    const float* b_hh   = (const float*)d_in[9];
    const float* W_out  = (const float*)d_in[10];
    const float* b_out  = (const float*)d_in[11];
    float* out = (float*)d_out;

    const int smem_bytes = (64*BSTR + GG*16*64 + 16*ASTR + 16*GSTR + 16*17 + 64 + 80)
                           * (int)sizeof(float); // 154,752 B
    cudaFuncSetAttribute(social_kernel, cudaFuncAttributeMaxDynamicSharedMemorySize, smem_bytes);
    social_kernel<<<NCTA, TPB, smem_bytes>>>(V, W_emb, b_emb, W_tens, b_tens,
                                             W_ih, b_ih, W_hh, b_hh, W_out, b_out, out);
}

// round 7
// speedup vs baseline: 3.5347x; 1.2191x over previous
#include <cuda_runtime.h>
#include <math.h>

#define TSEQ 128
#define NPED 256
#define RNN  128
#define EMB  64
#define GG   16
#define OUTD 5
#define NCTA 128
#define TPB  256
#define CAP2 256
#define KDIM 256
#define ASTR 260
#define BSTR 260
#define GSTR 68
#define HTS  20

// ---- persistent device scratch (no allocations allowed) ----
__device__ float d_h[2][NPED*RNN];            // double-buffered hidden state
__device__ float d_te_all[TSEQ*NPED*EMB];     // per-step social accumulators (pre-bias), zeroed once
__device__ float d_ie[TSEQ*NPED*EMB];         // precomputed input embeddings
__device__ int   d_pairs2[TSEQ*GG*CAP2];      // pair lists bucketed by (t, rowgroup(j)): (i<<8)|(jl<<4)|cell
__device__ int   d_pcnt2[TSEQ*GG];
__device__ int   d_cnt_l[8];                  // sense barrier: per-group arrival counts
__device__ int   d_cnt_r;                     // sense barrier: root count
__device__ volatile int d_sense;              // sense barrier (2 flips/launch -> returns to 0)
__device__ int   d_cntH[16];                  // per-rowt-team monotonic barrier: h ready (8 arrivals/step)
__device__ int   d_cntT[8];                   // global monotonic barrier: te ready (grouped)

// full sense-reversal barrier (cold path: preamble + epilogue only)
__device__ __forceinline__ void gbar(int* lsense, int grp) {
    __syncthreads();
    if (threadIdx.x == 0) {
        int s = 1 - *lsense;
        *lsense = s;
        __threadfence();
        if (atomicAdd(&d_cnt_l[grp], 1) == 15) {
            d_cnt_l[grp] = 0;
            __threadfence();
            if (atomicAdd(&d_cnt_r, 1) == 7) {
                d_cnt_r = 0;
                __threadfence();
                d_sense = s;
            }
        }
        while (d_sense != s) { }
        __threadfence();
    }
    __syncthreads();
}

// split-phase monotonic barriers: release-red arrive / acquire-load spin
__device__ __forceinline__ void arrive_rel(int* cnt) {
    __syncthreads();                    // CTA threads' prior writes ordered before leader's release
    if (threadIdx.x == 0)
        asm volatile("red.release.gpu.global.add.s32 [%0], 1;" :: "l"(cnt) : "memory");
}
__device__ __forceinline__ void waitH_team(const int* cnt, int target) {
    if (threadIdx.x == 0) {
        int v;
        do {
            asm volatile("ld.acquire.gpu.global.s32 %0, [%1];" : "=r"(v) : "l"(cnt) : "memory");
        } while (v < target);
    }
    __syncthreads();
}
__device__ __forceinline__ void waitT_all(const int* cnt, int target) {
    if (threadIdx.x == 0) {
        int s;
        do {
            s = 0;
            #pragma unroll
            for (int g = 0; g < 8; g++) {
                int v;
                asm volatile("ld.acquire.gpu.global.s32 %0, [%1];" : "=r"(v) : "l"(cnt + g) : "memory");
                s += v;
            }
        } while (s < target);
    }
    __syncthreads();
}

__device__ __forceinline__ float sigf(float x) {
    return __fdividef(1.f, 1.f + __expf(-x));
}
__device__ __forceinline__ float tanhfast(float x) {
    x = fminf(fmaxf(x, -15.f), 15.f);
    float e = __expf(2.f * x);
    return __fdividef(e - 1.f, e + 1.f);
}

template<int U0, int U1>
__device__ __forceinline__ void gemm_acc(float (&acc)[4][4], const float* Ab, const float* Bb) {
    #pragma unroll
    for (int u = U0; u < U1; u++) {
        float4 av[4], bv[4];
        #pragma unroll
        for (int i = 0; i < 4; i++) av[i] = *(const float4*)(Ab + i*ASTR + u*16);
        #pragma unroll
        for (int j = 0; j < 4; j++) bv[j] = *(const float4*)(Bb + j*BSTR + u*16);
        #pragma unroll
        for (int i = 0; i < 4; i++)
            #pragma unroll
            for (int j = 0; j < 4; j++) {
                acc[i][j] = fmaf(av[i].x, bv[j].x, acc[i][j]);
                acc[i][j] = fmaf(av[i].y, bv[j].y, acc[i][j]);
                acc[i][j] = fmaf(av[i].z, bv[j].z, acc[i][j]);
                acc[i][j] = fmaf(av[i].w, bv[j].w, acc[i][j]);
            }
    }
}

__global__ void __launch_bounds__(TPB, 1)
social_kernel(const float* __restrict__ V,
              const float* __restrict__ W_emb, const float* __restrict__ b_emb,
              const float* __restrict__ W_tens, const float* __restrict__ b_tens,
              const float* __restrict__ W_ih,  const float* __restrict__ b_ih,
              const float* __restrict__ W_hh,  const float* __restrict__ b_hh,
              const float* __restrict__ W_out, const float* __restrict__ b_out,
              float* __restrict__ out)
{
    extern __shared__ float sm[];
    float* B_s   = sm;                      // 64 x BSTR : persistent [W_ih|W_hh] column slice
    float* Wt_s  = B_s  + 64*BSTR;          // 16*16*64  : W_tens[cell][rl][e] for this CTA's r-slice
    float* A_s   = Wt_s + GG*16*64;         // 16 x ASTR : per-step A panel [ie|relu(te+b)|h]
    float* G_s   = A_s  + 16*ASTR;          // 16 x GSTR : gates tile
    float* h_tile= G_s  + 16*GSTR;          // 16 x HTS  : local h tile (stride 20 -> float4-aligned rows)
    float* bt_s  = h_tile + 16*HTS;         // 64        : b_tens
    float* Wout_s= bt_s + 64;               // 80        : W_out[o][r0:r0+16]
    __shared__ int pl_s[CAP2];
    __shared__ int scnt2[GG];
    __shared__ int lsense;

    const int tid = threadIdx.x;
    const int b   = blockIdx.x;
    const int gt  = b*TPB + tid;
    const int grp = b >> 4;

    if (tid == 0) lsense = 0;

    const int rowt = b >> 3, rt = b & 7;
    const int n0 = rowt*16, r0 = rt*16;
    const int nl = tid >> 4, rl = tid & 15;
    const int n  = n0 + nl,  r  = r0 + rl;

    // ---- zero recurrent state; zero this CTA's slice of d_te_all; init out with bias ----
    d_h[0][gt] = 0.f;
    {
        float* tz = d_te_all + b*(TSEQ*NPED*EMB/NCTA);
        #pragma unroll
        for (int k = tid; k < TSEQ*NPED*EMB/NCTA; k += TPB) tz[k] = 0.f;
        float* oz = out + b*1280;   // TSEQ*NPED*OUTD = 128*1280
        #pragma unroll
        for (int k = tid; k < 1280; k += TPB) oz[k] = b_out[k % OUTD];
    }

    // ---- precompute for frame t=b: positions, pair buckets by rowgroup(j), ie ----
    {
        const int t = b;
        float* xs = A_s;            // scratch reuse
        float* ys = A_s + NPED;
        xs[tid] = V[t*NPED + tid];
        ys[tid] = V[TSEQ*NPED + t*NPED + tid];
        if (tid < GG) scnt2[tid] = 0;
        __syncthreads();
        const float WB  = (float)(64.0/720.0), WBH = (float)(32.0/720.0);
        const float HBv = (float)(64.0/576.0), HBH = (float)(32.0/576.0);
        const float xi = xs[tid], yi = ys[tid];
        const int i = tid;
        for (int j = 0; j < NPED; j++) {
            if (j == i) continue;
            float dx = xs[j] - xi;
            float dy = ys[j] - yi;
            int cx = (int)floorf((dx + WBH)/WB*4.0f);
            int cy = (int)floorf((dy + HBH)/HBv*4.0f);
            if (cx >= 0 && cx < 4 && cy >= 0 && cy < 4) {
                int cell = cx + cy*4;
                int rj = j >> 4;
                int pos = atomicAdd(&scnt2[rj], 1);
                if (pos < CAP2)
                    d_pairs2[(t*GG + rj)*CAP2 + pos] = (i << 8) | ((j & 15) << 4) | cell;
            }
        }
        float* iep = d_ie + (t*NPED + i)*EMB;
        #pragma unroll 8
        for (int e = 0; e < EMB; e++) {
            float v = fmaf(W_emb[2*e], xi, fmaf(W_emb[2*e+1], yi, b_emb[e]));
            iep[e] = fmaxf(v, 0.f);
        }
        __syncthreads();
        if (tid < GG) d_pcnt2[t*GG + tid] = min(scnt2[tid], CAP2);
    }

    // ---- persistent smem weights ----
    for (int idx = tid; idx < 64*KDIM; idx += TPB) {
        int ql = idx >> 8, k = idx & 255;
        int q = (ql >> 4)*RNN + r0 + (ql & 15);
        B_s[ql*BSTR + k] = (k < RNN) ? W_ih[q*RNN + k] : W_hh[q*RNN + (k - RNN)];
    }
    for (int idx = tid; idx < GG*16*64; idx += TPB) {
        int e = idx & 63, rr = (idx >> 6) & 15, cell = idx >> 10;
        Wt_s[idx] = W_tens[e*(GG*RNN) + cell*RNN + r0 + rr];   // layout [cell][rl][e]
    }
    if (tid < EMB) bt_s[tid] = b_tens[tid];
    if (tid < OUTD*16) Wout_s[tid] = W_out[(tid >> 4)*RNN + r0 + (tid & 15)];

    // ---- per-thread recurrent registers: gate biases + cell state ----
    const float bi = b_ih[r]         + b_hh[r];
    const float bf = b_ih[RNN+r]     + b_hh[RNN+r];
    const float bg = b_ih[2*RNN+r]   + b_hh[2*RNN+r];
    const float bo = b_ih[3*RNN+r]   + b_hh[3*RNN+r];
    float creg = 0.f;

    gbar(&lsense, grp);   // full barrier: preamble done (h0, te0, pairs, ie, out-bias visible)

    const int ks   = tid & 3;       // split-K=4, interleaved slices (conflict-free)
    const int slot = tid >> 2;
    const int row4 = slot >> 4;
    const int q4   = slot & 15;

    for (int t = 0; t < TSEQ; t++) {
        const int pt = t & 1, pn = pt ^ 1;

        // ---- (0) h-independent: pair list for t+1, ie columns of A (all 256 threads) ----
        int cnt = 0;
        if (t < TSEQ-1) {
            cnt = d_pcnt2[(t+1)*GG + rowt];
            if (tid < cnt) pl_s[tid] = d_pairs2[((t+1)*GG + rowt)*CAP2 + tid];
        }
        {
            const float* iet = d_ie + t*NPED*EMB;
            const int col = tid & 63, mq = tid >> 6;
            #pragma unroll
            for (int mm = 0; mm < 4; mm++) {
                const int m = mq*4 + mm;
                A_s[m*ASTR + col] = iet[(n0 + m)*EMB + col];
            }
        }

        // ---- (1) wait for team h_t (single counter, 8 arrivals/step) ----
        waitH_team(d_cntH + rowt, 8*t);

        // ---- (2) stage h columns (all 256 threads, 8 rows each) ----
        {
            const float* hp = d_h[pt];
            const int col = tid & 127, mh = (tid >> 7)*8;
            #pragma unroll
            for (int mm = 0; mm < 8; mm++) {
                const int m = mh + mm;
                A_s[m*ASTR + 128 + col] = hp[(n0 + m)*RNN + col];
            }
        }
        __syncthreads();

        // ---- (3) GEMM part 1: ie (u 0..3) + h (u 8..15) columns ----
        float acc[4][4];
        #pragma unroll
        for (int i = 0; i < 4; i++)
            #pragma unroll
            for (int j = 0; j < 4; j++) acc[i][j] = 0.f;
        const float* Ab = A_s + (row4*4)*ASTR + ks*4;
        const float* Bb = B_s + (q4*4)*BSTR + ks*4;
        gemm_acc<0,4>(acc, Ab, Bb);
        gemm_acc<8,16>(acc, Ab, Bb);

        // ---- (4) wait for te_t (others' social hid under part 1) ----
        waitT_all(d_cntT, 128*t);

        // ---- (5) stage te columns (all 256 threads, 4 rows each) ----
        {
            const float* tep = d_te_all + t*NPED*EMB;
            const int col = tid & 63, mq = tid >> 6;
            #pragma unroll
            for (int mm = 0; mm < 4; mm++) {
                const int m = mq*4 + mm;
                A_s[m*ASTR + 64 + col] = fmaxf(tep[(n0 + m)*EMB + col] + bt_s[col], 0.f);
            }
        }
        __syncthreads();

        // ---- (6) GEMM part 2: te columns (u 4..7) ----
        gemm_acc<4,8>(acc, Ab, Bb);

        #pragma unroll
        for (int i = 0; i < 4; i++)
            #pragma unroll
            for (int j = 0; j < 4; j++) {
                float v = acc[i][j];
                v += __shfl_xor_sync(0xffffffffu, v, 1);
                v += __shfl_xor_sync(0xffffffffu, v, 2);
                acc[i][j] = v;
            }
        if (ks == 0) {
            #pragma unroll
            for (int i = 0; i < 4; i++)
                #pragma unroll
                for (int j = 0; j < 4; j++)
                    G_s[(row4*4+i)*GSTR + q4*4 + j] = acc[i][j];
        }
        __syncthreads();

        // ---- (7) LSTM pointwise (local) ----
        float hv;
        {
            const float* gs = G_s + nl*GSTR + rl;
            float gi = gs[0]  + bi;
            float gf = gs[16] + bf;
            float gg = gs[32] + bg;
            float go = gs[48] + bo;
            float si = sigf(gi);
            float sf = sigf(gf);
            float so = sigf(go);
            creg = sf*creg + si*tanhfast(gg);
            hv = so*tanhfast(creg);
            h_tile[nl*HTS + rl] = hv;
            d_h[pn][n*RNN + r] = hv;
        }

        // ---- (8) announce h_{t+1} to team ----
        arrive_rel(d_cntH + rowt);

        // ---- (9) social partial sums for te_{t+1} (local h_tile, off critical path) ----
        if (t < TSEQ-1) {
            float* tew = d_te_all + (t+1)*NPED*EMB;
            const int pg = tid >> 6;   // 4 pair-groups of 64 threads
            const int e  = tid & 63;
            for (int p = pg; p < cnt; p += 4) {
                const int pr = pl_s[p];
                const int i  = pr >> 8, jl = (pr >> 4) & 15, cell = pr & 15;
                const float* wt = Wt_s + cell*(16*64) + e;
                const float4* h4 = (const float4*)(h_tile + jl*HTS);
                float s = 0.f;
                #pragma unroll
                for (int q = 0; q < 4; q++) {
                    float4 hq = h4[q];
                    const float* wq = wt + q*4*64;
                    s = fmaf(wq[0],   hq.x, s);
                    s = fmaf(wq[64],  hq.y, s);
                    s = fmaf(wq[128], hq.z, s);
                    s = fmaf(wq[192], hq.w, s);
                }
                atomicAdd(tew + i*EMB + e, s);
            }
        }

        // ---- (10) announce te_{t+1} globally ----
        arrive_rel(d_cntT + grp);

        // ---- (11) output projection for step t (pure output, off critical path) ----
        {
            #pragma unroll
            for (int o = 0; o < OUTD; o++) {
                float pv = hv * Wout_s[o*16 + rl];
                pv += __shfl_xor_sync(0xffffffffu, pv, 8);
                pv += __shfl_xor_sync(0xffffffffu, pv, 4);
                pv += __shfl_xor_sync(0xffffffffu, pv, 2);
                pv += __shfl_xor_sync(0xffffffffu, pv, 1);
                if (rl == 0) atomicAdd(out + (t*NPED + n)*OUTD + o, pv);
            }
        }
    }

    gbar(&lsense, grp);  // full barrier; sense flips total = 2 (returns to 0)

    // reset monotonic counters for the next graph replay
    if (b == 0 && tid < 16) d_cntH[tid] = 0;
    if (b == 0 && tid < 8)  d_cntT[tid] = 0;

    // ---- epilogue: hT (in d_h[0] after t=127), cT from registers ----
    {
        float* hT = out + TSEQ*NPED*OUTD;
        float* cT = hT + NPED*RNN;
        hT[gt] = d_h[0][gt];
        cT[n*RNN + r] = creg;
    }
}

extern "C" void kernel_launch(void* const* d_in, const int* in_sizes, int n_in,
                              void* d_out, int out_size) {
    const float* V      = (const float*)d_in[0];
    // d_in[1] = PedsList (identity arange) -- unused by construction
    const float* W_emb  = (const float*)d_in[2];
    const float* b_emb  = (const float*)d_in[3];
    const float* W_tens = (const float*)d_in[4];
    const float* b_tens = (const float*)d_in[5];
    const float* W_ih   = (const float*)d_in[6];
    const float* b_ih   = (const float*)d_in[7];
    const float* W_hh   = (const float*)d_in[8];
    const float* b_hh   = (const float*)d_in[9];
    const float* W_out  = (const float*)d_in[10];
    const float* b_out  = (const float*)d_in[11];
    float* out = (float*)d_out;

    const int smem_bytes = (64*BSTR + GG*16*64 + 16*ASTR + 16*GSTR + 16*HTS + 64 + 80)
                           * (int)sizeof(float); // ~154.9 KB
    cudaFuncSetAttribute(social_kernel, cudaFuncAttributeMaxDynamicSharedMemorySize, smem_bytes);
    social_kernel<<<NCTA, TPB, smem_bytes>>>(V, W_emb, b_emb, W_tens, b_tens,
                                             W_ih, b_ih, W_hh, b_hh, W_out, b_out, out);
}